// round 7
// baseline (speedup 1.0000x reference)
#include <cuda_runtime.h>
#include <cstdint>

#define NB    5
#define HWPX  65536
#define NP    (NB*HWPX)
#define NCH   256
#define NBUCK 32768         // valid dsc < 0x80000000 -> bucket < 32768
#define NTILE 32            // 32 tiles of 1024 buckets per batch
#define WCAP  4096

// ---- static device scratch (allocation-free) ----
__device__ unsigned int       g_dsc[NP];           // descending-order key of best utility
__device__ unsigned char      g_g8[NP];            // argmax group 0/1/2
__device__ signed char        g_selmap[NP];        // accepted group or -1
__device__ unsigned long long g_hist[NB*NBUCK];    // packed: cost | c1<<20 | c2<<40
__device__ unsigned int       g_winbits[NP/32];    // accepted-window-pixel bitmap (40KB)
__device__ int                g_b0[NB];

__device__ __forceinline__ float load_budget(const void* ptr) {
    int iv = *(const int*)ptr;                       // int32 or float32 scalar
    if (iv > 0 && iv < 100000000) return (float)iv;
    return __int_as_float(iv);
}
__device__ __forceinline__ int cost_of(int g) { return (g == 0) ? 4 : (g == 1) ? 2 : 1; }

__device__ __forceinline__ void do_pixel(int p, float u0, float u1, float u2,
                                         unsigned* dsc_o, unsigned char* g_o) {
    int g = 0; float bu = u0;
    if (u1 > bu) { bu = u1; g = 1; }   // strict >: first max wins (jnp.argmax)
    if (u2 > bu) { bu = u2; g = 2; }
    bool valid = bu > 0.0f;
    unsigned int x = __float_as_uint(bu);
    unsigned int dsc = ~((x & 0x80000000u) ? ~x : (x | 0x80000000u)); // descending map
    if (!valid) dsc = 0xFFFFFFFFu;
    *dsc_o = dsc; *g_o = (unsigned char)g;
    if (valid) {
        unsigned long long inc = (unsigned long long)cost_of(g)
            | ((unsigned long long)(g == 1) << 20)
            | ((unsigned long long)(g == 2) << 40);
        atomicAdd(&g_hist[(p >> 16) * NBUCK + (dsc >> 16)], inc);
    }
}

// ---- per-pixel argmax + packed histogram, 4 px / thread vectorized ----
__global__ void kArgmax(const float* __restrict__ util) {
    int q  = blockIdx.x * blockDim.x + threadIdx.x;   // NP/4 threads
    int p0 = q << 2;
    const float4* u = (const float4*)(util + 3 * (size_t)p0);
    float4 a = u[0], b = u[1], c = u[2];
    unsigned d4[4]; unsigned char gg[4];
    do_pixel(p0 + 0, a.x, a.y, a.z, &d4[0], &gg[0]);
    do_pixel(p0 + 1, a.w, b.x, b.y, &d4[1], &gg[1]);
    do_pixel(p0 + 2, b.z, b.w, c.x, &d4[2], &gg[2]);
    do_pixel(p0 + 3, c.y, c.z, c.w, &d4[3], &gg[3]);
    *(uint4*)(g_dsc + p0)  = make_uint4(d4[0], d4[1], d4[2], d4[3]);
    *(uchar4*)(g_g8 + p0)  = make_uchar4(gg[0], gg[1], gg[2], gg[3]);
}

// ---- fused selection: tile sums + crossing + window + sort + greedy replay ----
// One block of 1024 threads per batch. Emits g_b0[b] and the accepted-window bitmap.
__global__ void kSelect(const void* __restrict__ budget_p) {
    __shared__ unsigned s_tile[NTILE];
    __shared__ unsigned s_wsum[32];
    __shared__ int s_ctile, s_b0, s_b1, s_n;
    __shared__ unsigned s_cumbase, s_Sb;
    __shared__ unsigned long long sk[WCAP];   // 32KB window list

    int b = blockIdx.x, t = threadIdx.x;
    int wid = t >> 5, lane = t & 31;
    float budget = load_budget(budget_p) / (float)NB;
    const unsigned long long* hist = g_hist + (size_t)b * NBUCK;

    // tile sums: warp w sums tile w (1024 buckets), coalesced
    unsigned sum = 0;
    #pragma unroll 4
    for (int j = 0; j < 32; j++)
        sum += (unsigned)(hist[wid*1024 + j*32 + lane] & 0xFFFFFu);
    #pragma unroll
    for (int off = 16; off > 0; off >>= 1) sum += __shfl_down_sync(0xffffffffu, sum, off);
    if (lane == 0) s_tile[wid] = sum;
    if (t == 0) { s_ctile = -1; s_cumbase = 0; s_b0 = NBUCK; s_Sb = 0; s_b1 = -1; s_n = 0; }
    __syncthreads();

    if (t == 0) {   // tile-level crossing
        unsigned cum = 0;
        for (int q = 0; q < NTILE; q++) {
            unsigned c = s_tile[q];
            if ((float)(cum + c) > budget) { s_ctile = q; s_cumbase = cum; break; }
            cum += c;
        }
    }
    __syncthreads();
    int ctile = s_ctile;

    if (ctile >= 0) {   // in-tile block scan over 1024 buckets
        unsigned c = (unsigned)(hist[ctile*1024 + t] & 0xFFFFFu);
        unsigned inc = c;
        #pragma unroll
        for (int off = 1; off < 32; off <<= 1) {
            unsigned v = __shfl_up_sync(0xffffffffu, inc, off);
            if (lane >= off) inc += v;
        }
        if (lane == 31) s_wsum[wid] = inc;
        __syncthreads();
        if (wid == 0) {
            unsigned w = s_wsum[lane];
            #pragma unroll
            for (int off = 1; off < 32; off <<= 1) {
                unsigned v = __shfl_up_sync(0xffffffffu, w, off);
                if (lane >= off) w += v;
            }
            s_wsum[lane] = w;
        }
        __syncthreads();
        unsigned woff = (wid > 0) ? s_wsum[wid-1] : 0u;
        unsigned inclT = s_cumbase + woff + inc;
        unsigned excl  = inclT - c;
        if ((float)inclT > budget && (float)excl <= budget) {   // unique crossing
            s_b0 = ctile*1024 + t;
            s_Sb = excl;
        }
        __syncthreads();
    }

    int b0 = s_b0;
    if (t == 0) g_b0[b] = b0;
    if (b0 >= NBUCK) return;   // no crossing: all valid accepted, bitmap stays empty

    if (wid == 0) {   // extend window until >=8 cost-1 items beyond b0
        int c2cum = 0, pos = b0 + 1, b1 = NBUCK-1; bool done = false;
        while (!done && pos < NBUCK) {
            int idx = pos + lane;
            unsigned long long h = (idx < NBUCK) ? hist[idx] : 0ull;
            int k = (int)((h >> 40) & 0xFFFFFull);
            int inck = k;
            #pragma unroll
            for (int off = 1; off < 32; off <<= 1) {
                int v = __shfl_up_sync(0xffffffffu, inck, off);
                if (lane >= off) inck += v;
            }
            int tot = __shfl_sync(0xffffffffu, inck, 31);
            unsigned m = __ballot_sync(0xffffffffu, c2cum + inck >= 8);
            if (m) { b1 = min(pos + (__ffs(m) - 1), NBUCK-1); done = true; }
            else   { c2cum += tot; pos += 32; }
        }
        if (lane == 0) s_b1 = b1;
    }
    __syncthreads();
    int b1 = s_b1;

    // gather window items straight from g_dsc (coalesced uint4)
    const uint4* dscv = (const uint4*)(g_dsc + b * HWPX);
    for (int i = t; i < HWPX/4; i += 1024) {
        uint4 d = dscv[i];
        unsigned da[4] = {d.x, d.y, d.z, d.w};
        #pragma unroll
        for (int k = 0; k < 4; k++) {
            int bucket = (int)(da[k] >> 16);           // valid implied by bucket<=b1<32768
            if (bucket >= b0 && bucket <= b1) {
                int pix = i*4 + k;
                int g = (int)g_g8[b*HWPX + pix];
                int idx = atomicAdd(&s_n, 1);
                if (idx < WCAP)
                    sk[idx] = ((unsigned long long)da[k] << 24)
                            | ((unsigned long long)pix << 8) | (unsigned long long)g;
            }
        }
    }
    __syncthreads();
    int n = min(s_n, WCAP);

    // exact ranking sort (unique keys -> permutation)
    unsigned long long myk[4]; int myr[4]; int cnt = 0;
    for (int i = t; i < n; i += 1024) {
        unsigned long long k = sk[i];
        int r = 0;
        for (int j = 0; j < n; j++) r += (sk[j] < k);
        myk[cnt] = k; myr[cnt] = r; cnt++;
    }
    __syncthreads();
    for (int q = 0; q < cnt; q++) sk[myr[q]] = myk[q];
    __syncthreads();

    if (t == 0) {   // greedy replay -> accepted-window bitmap
        float usage = (float)s_Sb;
        for (int i = 0; i < n; i++) {
            if (usage + 1.0f > budget) break;          // nothing else fits
            unsigned long long k = sk[i];
            int g   = (int)(k & 0xFFu);
            int pix = (int)((k >> 8) & 0xFFFFu);
            float c = (float)cost_of(g);
            if (usage + c <= budget) {
                usage += c;
                int p = b * HWPX + pix;
                atomicOr(&g_winbits[p >> 5], 1u << (p & 31));
            }
        }
    }
}

// ---- final per-pixel decision (4 px / thread, no atomics) ----
__global__ void kGather(float* __restrict__ out_sel) {
    int q = blockIdx.x * blockDim.x + threadIdx.x;   // NP/4 threads
    int p0 = q << 2;
    int b = p0 >> 16;
    uint4 d4 = *(const uint4*)(g_dsc + p0);
    uchar4 gg = *(const uchar4*)(g_g8 + p0);
    int b0 = g_b0[b];
    unsigned wb = g_winbits[p0 >> 5];
    unsigned dsc[4] = {d4.x, d4.y, d4.z, d4.w};
    int gv[4] = {gg.x, gg.y, gg.z, gg.w};
    signed char sm[4]; float so[4];
    #pragma unroll
    for (int k = 0; k < 4; k++) {
        bool acc = (dsc[k] < 0x80000000u && (int)(dsc[k] >> 16) < b0)
                 || ((wb >> ((p0 & 31) + k)) & 1u);
        sm[k] = acc ? (signed char)gv[k] : (signed char)-1;
        so[k] = acc ? (float)gv[k] : -1.0f;
    }
    *(char4*)(g_selmap + p0) = make_char4(sm[0], sm[1], sm[2], sm[3]);
    *(float4*)(out_sel + p0) = make_float4(so[0], so[1], so[2], so[3]);
}

// ---- big HBM-bound masked copy: frozen R3 winner (1 thread = 1 float4) ----
__global__ void kMaskedCopy(const float* __restrict__ collab, float* __restrict__ out) {
    int tid = blockIdx.x * blockDim.x + threadIdx.x;
    int row = tid >> 14;               // b*256 + c
    int o   = (tid & 16383) << 2;      // hw offset, multiple of 4
    int c   = row & 255;
    int b   = row >> 8;
    int grp = (c < 64) ? 0 : (c < 192) ? 1 : 2;
    char4 s4 = *(const char4*)(g_selmap + b * HWPX + o);
    bool m0 = (s4.x == grp), m1 = (s4.y == grp), m2 = (s4.z == grp), m3 = (s4.w == grp);
    float4 v = make_float4(0.f, 0.f, 0.f, 0.f);
    size_t idx = ((size_t)row << 16) + (size_t)o;
    if (m0 | m1 | m2 | m3) {
        v = *(const float4*)(collab + idx);
        if (!m0) v.x = 0.f;
        if (!m1) v.y = 0.f;
        if (!m2) v.z = 0.f;
        if (!m3) v.w = 0.f;
    }
    *(float4*)(out + idx) = v;
}

extern "C" void kernel_launch(void* const* d_in, const int* in_sizes, int n_in,
                              void* d_out, int out_size) {
    const float* collab = (const float*)d_in[0];
    const float* util   = (const float*)d_in[1];
    const void*  budget = d_in[2];
    float* out     = (float*)d_out;
    float* out_sel = out + (size_t)NP * NCH;

    void *p_hist, *p_wb;
    cudaGetSymbolAddress(&p_hist, g_hist);
    cudaGetSymbolAddress(&p_wb,   g_winbits);
    cudaMemsetAsync(p_hist, 0, sizeof(unsigned long long) * NB * NBUCK);
    cudaMemsetAsync(p_wb,   0, sizeof(unsigned int) * (NP/32));

    kArgmax<<<NP/4/256, 256>>>(util);
    kSelect<<<NB, 1024>>>(budget);
    kGather<<<NP/4/256, 256>>>(out_sel);
    kMaskedCopy<<<(NP/4)*NCH/256, 256>>>(collab, out);
}

// round 8
// speedup vs baseline: 1.0264x; 1.0264x over previous
#include <cuda_runtime.h>
#include <cstdint>

#define NB    5
#define HWPX  65536
#define NP    (NB*HWPX)
#define NCH   256
#define NBUCK 32768         // valid dsc < 0x80000000 -> bucket < 32768
#define NTILE 32            // 32 tiles of 1024 buckets per batch
#define WCAP  4096

// ---- static device scratch (allocation-free; zero-initialized at load) ----
__device__ unsigned int       g_dsc[NP];           // descending-order key of best utility
__device__ unsigned char      g_g8[NP];            // argmax group 0/1/2
__device__ signed char        g_selmap[NP];        // accepted group or -1
__device__ unsigned long long g_hist[NB*NBUCK];    // packed: cost | c1<<20 | c2<<40
__device__ unsigned long long g_window[NB*WCAP];
__device__ int                g_wcount[NB];
__device__ int                g_b0[NB], g_b1[NB];
__device__ float              g_Sbefore[NB];

__device__ __forceinline__ float load_budget(const void* ptr) {
    int iv = *(const int*)ptr;                       // int32 or float32 scalar
    if (iv > 0 && iv < 100000000) return (float)iv;
    return __int_as_float(iv);
}
__device__ __forceinline__ int cost_of(int g) { return (g == 0) ? 4 : (g == 1) ? 2 : 1; }

__device__ __forceinline__ void do_pixel(int p, float u0, float u1, float u2,
                                         unsigned* dsc_o, unsigned char* g_o) {
    int g = 0; float bu = u0;
    if (u1 > bu) { bu = u1; g = 1; }   // strict >: first max wins (jnp.argmax)
    if (u2 > bu) { bu = u2; g = 2; }
    bool valid = bu > 0.0f;
    unsigned int x = __float_as_uint(bu);
    unsigned int dsc = ~((x & 0x80000000u) ? ~x : (x | 0x80000000u)); // descending map
    if (!valid) dsc = 0xFFFFFFFFu;
    *dsc_o = dsc; *g_o = (unsigned char)g;
    if (valid) {
        unsigned long long inc = (unsigned long long)cost_of(g)
            | ((unsigned long long)(g == 1) << 20)
            | ((unsigned long long)(g == 2) << 40);
        atomicAdd(&g_hist[(p >> 16) * NBUCK + (dsc >> 16)], inc);
    }
}

// ---- per-pixel argmax + packed histogram, 4 px / thread vectorized ----
__global__ void kArgmax(const float* __restrict__ util) {
    int q  = blockIdx.x * blockDim.x + threadIdx.x;   // NP/4 threads
    int p0 = q << 2;
    const float4* u = (const float4*)(util + 3 * (size_t)p0);
    float4 a = u[0], b = u[1], c = u[2];
    unsigned d4[4]; unsigned char gg[4];
    do_pixel(p0 + 0, a.x, a.y, a.z, &d4[0], &gg[0]);
    do_pixel(p0 + 1, a.w, b.x, b.y, &d4[1], &gg[1]);
    do_pixel(p0 + 2, b.z, b.w, c.x, &d4[2], &gg[2]);
    do_pixel(p0 + 3, c.y, c.z, c.w, &d4[3], &gg[3]);
    *(uint4*)(g_dsc + p0)  = make_uint4(d4[0], d4[1], d4[2], d4[3]);
    *(uchar4*)(g_g8 + p0)  = make_uchar4(gg[0], gg[1], gg[2], gg[3]);
}

// ---- 1 block (1024 thr) per batch: tile sums + crossing b0 + window end b1 ----
__global__ void kFindWindow(const void* __restrict__ budget_p) {
    __shared__ unsigned s_tile[NTILE];
    __shared__ unsigned s_wsum[32];
    __shared__ int s_ctile, s_b0;
    __shared__ unsigned s_cumbase, s_Sb;

    int b = blockIdx.x, t = threadIdx.x;
    int wid = t >> 5, lane = t & 31;
    float budget = load_budget(budget_p) / (float)NB;
    const unsigned long long* hist = g_hist + (size_t)b * NBUCK;

    // warp w sums tile w (1024 buckets), coalesced
    unsigned sum = 0;
    #pragma unroll 4
    for (int j = 0; j < 32; j++)
        sum += (unsigned)(hist[wid*1024 + j*32 + lane] & 0xFFFFFu);
    #pragma unroll
    for (int off = 16; off > 0; off >>= 1) sum += __shfl_down_sync(0xffffffffu, sum, off);
    if (lane == 0) s_tile[wid] = sum;
    if (t == 0) { s_ctile = -1; s_cumbase = 0; s_b0 = NBUCK; s_Sb = 0; }
    __syncthreads();

    if (t == 0) {   // tile-level crossing
        unsigned cum = 0;
        for (int q = 0; q < NTILE; q++) {
            unsigned c = s_tile[q];
            if ((float)(cum + c) > budget) { s_ctile = q; s_cumbase = cum; break; }
            cum += c;
        }
    }
    __syncthreads();
    int ctile = s_ctile;

    if (ctile >= 0) {   // in-tile block scan over 1024 buckets
        unsigned c = (unsigned)(hist[ctile*1024 + t] & 0xFFFFFu);
        unsigned inc = c;
        #pragma unroll
        for (int off = 1; off < 32; off <<= 1) {
            unsigned v = __shfl_up_sync(0xffffffffu, inc, off);
            if (lane >= off) inc += v;
        }
        if (lane == 31) s_wsum[wid] = inc;
        __syncthreads();
        if (wid == 0) {
            unsigned w = s_wsum[lane];
            #pragma unroll
            for (int off = 1; off < 32; off <<= 1) {
                unsigned v = __shfl_up_sync(0xffffffffu, w, off);
                if (lane >= off) w += v;
            }
            s_wsum[lane] = w;
        }
        __syncthreads();
        unsigned woff = (wid > 0) ? s_wsum[wid-1] : 0u;
        unsigned inclT = s_cumbase + woff + inc;
        unsigned excl  = inclT - c;
        if ((float)inclT > budget && (float)excl <= budget) {   // unique crossing
            s_b0 = ctile*1024 + t;
            s_Sb = excl;
        }
        __syncthreads();
    }

    int b0 = s_b0;
    if (wid == 0 && b0 < NBUCK) {
        // extend window bucket-by-bucket until >=8 cost-1 items beyond b0
        int c2cum = 0, pos = b0 + 1, b1 = NBUCK-1; bool done = false;
        while (!done && pos < NBUCK) {
            int idx = pos + lane;
            unsigned long long h = (idx < NBUCK) ? hist[idx] : 0ull;
            int k = (int)((h >> 40) & 0xFFFFFull);
            int inck = k;
            #pragma unroll
            for (int off = 1; off < 32; off <<= 1) {
                int v = __shfl_up_sync(0xffffffffu, inck, off);
                if (lane >= off) inck += v;
            }
            int tot = __shfl_sync(0xffffffffu, inck, 31);
            unsigned m = __ballot_sync(0xffffffffu, c2cum + inck >= 8);
            if (m) { b1 = min(pos + (__ffs(m) - 1), NBUCK-1); done = true; }
            else   { c2cum += tot; pos += 32; }
        }
        if (lane == 0) g_b1[b] = b1;
    }
    if (t == 0) {
        g_b0[b] = b0;
        g_Sbefore[b] = (float)s_Sb;
        g_wcount[b] = 0;                 // reset for kGather's atomics
        if (b0 == NBUCK) g_b1[b] = -1;   // no crossing: accept all valid
    }
}

// ---- phase-1 decisions + gather window items (4 px / thread) ----
__global__ void kGather(float* __restrict__ out_sel) {
    int q = blockIdx.x * blockDim.x + threadIdx.x;   // NP/4 threads
    int p0 = q << 2;
    int b = p0 >> 16;
    uint4 d4 = *(const uint4*)(g_dsc + p0);
    uchar4 gg = *(const uchar4*)(g_g8 + p0);
    int b0 = g_b0[b], b1 = g_b1[b];
    unsigned dsc[4] = {d4.x, d4.y, d4.z, d4.w};
    int gv[4] = {gg.x, gg.y, gg.z, gg.w};
    signed char sm[4]; float so[4];
    #pragma unroll
    for (int k = 0; k < 4; k++) {
        bool valid = dsc[k] < 0x80000000u;
        int bucket = (int)(dsc[k] >> 16);
        bool acc = valid && bucket < b0;
        sm[k] = acc ? (signed char)gv[k] : (signed char)-1;
        so[k] = acc ? (float)gv[k] : -1.0f;
        if (valid && bucket >= b0 && bucket <= b1) {
            int i = atomicAdd(&g_wcount[b], 1);
            if (i < WCAP)
                g_window[b*WCAP + i] = ((unsigned long long)dsc[k] << 24)
                    | ((unsigned long long)((p0 + k) & 0xFFFF) << 8)
                    | (unsigned long long)gv[k];
        }
    }
    *(char4*)(g_selmap + p0) = make_char4(sm[0], sm[1], sm[2], sm[3]);
    *(float4*)(out_sel + p0) = make_float4(so[0], so[1], so[2], so[3]);
}

// ---- exact ranking sort + sequential greedy replay over the window ----
__global__ void kWindow(const void* __restrict__ budget_p, float* __restrict__ out_sel) {
    __shared__ unsigned long long sk[WCAP];
    int b = blockIdx.x, t = threadIdx.x;
    int n = min(g_wcount[b], WCAP);
    for (int i = t; i < n; i += 512) sk[i] = g_window[b*WCAP + i];
    __syncthreads();
    unsigned long long myk[8]; int myr[8]; int cnt = 0;
    for (int i = t; i < n; i += 512) {
        unsigned long long k = sk[i];
        int r = 0;
        for (int j = 0; j < n; j++) r += (sk[j] < k);   // unique keys -> permutation
        myk[cnt] = k; myr[cnt] = r; cnt++;
    }
    __syncthreads();
    for (int q = 0; q < cnt; q++) sk[myr[q]] = myk[q];
    __syncthreads();
    if (t == 0) {
        float budget = load_budget(budget_p) / (float)NB;
        float usage  = g_Sbefore[b];
        for (int i = 0; i < n; i++) {
            if (usage + 1.0f > budget) break;          // nothing else fits
            unsigned long long k = sk[i];
            int g   = (int)(k & 0xFFu);
            int pix = (int)((k >> 8) & 0xFFFFu);
            float c = (float)cost_of(g);
            if (usage + c <= budget) {
                usage += c;
                int p = b * HWPX + pix;
                g_selmap[p] = (signed char)g;
                out_sel[p]  = (float)g;
            }
        }
    }
}

// ---- big HBM-bound masked copy (frozen R3 winner) + hist re-zero for next replay ----
__global__ void kMaskedCopy(const float* __restrict__ collab, float* __restrict__ out) {
    int tid = blockIdx.x * blockDim.x + threadIdx.x;
    if (tid < (int)(sizeof(g_hist)/sizeof(uint4)))      // 81920 threads zero g_hist
        ((uint4*)g_hist)[tid] = make_uint4(0u, 0u, 0u, 0u);
    int row = tid >> 14;               // b*256 + c
    int o   = (tid & 16383) << 2;      // hw offset, multiple of 4
    int c   = row & 255;
    int b   = row >> 8;
    int grp = (c < 64) ? 0 : (c < 192) ? 1 : 2;
    char4 s4 = *(const char4*)(g_selmap + b * HWPX + o);
    bool m0 = (s4.x == grp), m1 = (s4.y == grp), m2 = (s4.z == grp), m3 = (s4.w == grp);
    float4 v = make_float4(0.f, 0.f, 0.f, 0.f);
    size_t idx = ((size_t)row << 16) + (size_t)o;
    if (m0 | m1 | m2 | m3) {
        v = *(const float4*)(collab + idx);
        if (!m0) v.x = 0.f;
        if (!m1) v.y = 0.f;
        if (!m2) v.z = 0.f;
        if (!m3) v.w = 0.f;
    }
    *(float4*)(out + idx) = v;
}

extern "C" void kernel_launch(void* const* d_in, const int* in_sizes, int n_in,
                              void* d_out, int out_size) {
    const float* collab = (const float*)d_in[0];
    const float* util   = (const float*)d_in[1];
    const void*  budget = d_in[2];
    float* out     = (float*)d_out;
    float* out_sel = out + (size_t)NP * NCH;

    kArgmax<<<NP/4/256, 256>>>(util);
    kFindWindow<<<NB, 1024>>>(budget);
    kGather<<<NP/4/256, 256>>>(out_sel);
    kWindow<<<NB, 512>>>(budget, out_sel);
    kMaskedCopy<<<(NP/4)*NCH/256, 256>>>(collab, out);
}

// round 9
// speedup vs baseline: 1.1297x; 1.1006x over previous
#include <cuda_runtime.h>
#include <cstdint>

#define NB    5
#define HWPX  65536
#define NP    (NB*HWPX)
#define NCH   256
#define NBUCK 32768         // valid dsc < 0x80000000 -> bucket < 32768
#define NTILE 32            // 32 tiles of 1024 buckets per batch
#define WCAP  4096

// ---- static device scratch (allocation-free; zero-initialized at load) ----
__device__ unsigned int       g_dsc[NP];           // descending-order key of best utility
__device__ unsigned char      g_g8[NP];            // argmax group 0/1/2
__device__ signed char        g_selmap[NP];        // accepted group or -1
__device__ unsigned long long g_hist[NB*NBUCK];    // packed: cost | c1<<20 | c2<<40
__device__ unsigned long long g_window[NB*WCAP];
__device__ int                g_wcount[NB];
__device__ int                g_b0[NB], g_b1[NB];
__device__ float              g_Sbefore[NB];

__device__ __forceinline__ float load_budget(const void* ptr) {
    int iv = *(const int*)ptr;                       // int32 or float32 scalar
    if (iv > 0 && iv < 100000000) return (float)iv;
    return __int_as_float(iv);
}
__device__ __forceinline__ int cost_of(int g) { return (g == 0) ? 4 : (g == 1) ? 2 : 1; }

__device__ __forceinline__ void do_pixel(int p, float u0, float u1, float u2,
                                         unsigned* dsc_o, unsigned char* g_o) {
    int g = 0; float bu = u0;
    if (u1 > bu) { bu = u1; g = 1; }   // strict >: first max wins (jnp.argmax)
    if (u2 > bu) { bu = u2; g = 2; }
    bool valid = bu > 0.0f;
    unsigned int x = __float_as_uint(bu);
    unsigned int dsc = ~((x & 0x80000000u) ? ~x : (x | 0x80000000u)); // descending map
    if (!valid) dsc = 0xFFFFFFFFu;
    *dsc_o = dsc; *g_o = (unsigned char)g;
    if (valid) {
        unsigned long long inc = (unsigned long long)cost_of(g)
            | ((unsigned long long)(g == 1) << 20)
            | ((unsigned long long)(g == 2) << 40);
        atomicAdd(&g_hist[(p >> 16) * NBUCK + (dsc >> 16)], inc);
    }
}

// ---- per-pixel argmax + packed histogram, 2 px / thread ----
__global__ void kArgmax(const float* __restrict__ util) {
    int q  = blockIdx.x * blockDim.x + threadIdx.x;   // NP/2 threads
    int p0 = q << 1;
    const float2* u = (const float2*)(util + 3 * (size_t)p0);   // 6 floats = 3x float2
    float2 a = u[0], b = u[1], c = u[2];
    unsigned d2[2]; unsigned char gg[2];
    do_pixel(p0 + 0, a.x, a.y, b.x, &d2[0], &gg[0]);
    do_pixel(p0 + 1, b.y, c.x, c.y, &d2[1], &gg[1]);
    *(uint2*)(g_dsc + p0) = make_uint2(d2[0], d2[1]);
    *(uchar2*)(g_g8 + p0) = make_uchar2(gg[0], gg[1]);
}

// ---- 1 block (1024 thr) per batch: tile sums + crossing b0 + window end b1 ----
__global__ void kFindWindow(const void* __restrict__ budget_p) {
    __shared__ unsigned s_tile[NTILE];
    __shared__ unsigned s_wsum[32];
    __shared__ int s_ctile, s_b0;
    __shared__ unsigned s_cumbase, s_Sb;

    int b = blockIdx.x, t = threadIdx.x;
    int wid = t >> 5, lane = t & 31;
    float budget = load_budget(budget_p) / (float)NB;
    const unsigned long long* hist = g_hist + (size_t)b * NBUCK;

    // warp w sums tile w (1024 buckets), coalesced
    unsigned sum = 0;
    #pragma unroll 4
    for (int j = 0; j < 32; j++)
        sum += (unsigned)(hist[wid*1024 + j*32 + lane] & 0xFFFFFu);
    #pragma unroll
    for (int off = 16; off > 0; off >>= 1) sum += __shfl_down_sync(0xffffffffu, sum, off);
    if (lane == 0) s_tile[wid] = sum;
    if (t == 0) { s_ctile = -1; s_cumbase = 0; s_b0 = NBUCK; s_Sb = 0; }
    __syncthreads();

    if (t == 0) {   // tile-level crossing
        unsigned cum = 0;
        for (int q = 0; q < NTILE; q++) {
            unsigned c = s_tile[q];
            if ((float)(cum + c) > budget) { s_ctile = q; s_cumbase = cum; break; }
            cum += c;
        }
    }
    __syncthreads();
    int ctile = s_ctile;

    if (ctile >= 0) {   // in-tile block scan over 1024 buckets
        unsigned c = (unsigned)(hist[ctile*1024 + t] & 0xFFFFFu);
        unsigned inc = c;
        #pragma unroll
        for (int off = 1; off < 32; off <<= 1) {
            unsigned v = __shfl_up_sync(0xffffffffu, inc, off);
            if (lane >= off) inc += v;
        }
        if (lane == 31) s_wsum[wid] = inc;
        __syncthreads();
        if (wid == 0) {
            unsigned w = s_wsum[lane];
            #pragma unroll
            for (int off = 1; off < 32; off <<= 1) {
                unsigned v = __shfl_up_sync(0xffffffffu, w, off);
                if (lane >= off) w += v;
            }
            s_wsum[lane] = w;
        }
        __syncthreads();
        unsigned woff = (wid > 0) ? s_wsum[wid-1] : 0u;
        unsigned inclT = s_cumbase + woff + inc;
        unsigned excl  = inclT - c;
        if ((float)inclT > budget && (float)excl <= budget) {   // unique crossing
            s_b0 = ctile*1024 + t;
            s_Sb = excl;
        }
        __syncthreads();
    }

    int b0 = s_b0;
    if (wid == 0 && b0 < NBUCK) {
        // extend window bucket-by-bucket until >=8 cost-1 items beyond b0
        int c2cum = 0, pos = b0 + 1, b1 = NBUCK-1; bool done = false;
        while (!done && pos < NBUCK) {
            int idx = pos + lane;
            unsigned long long h = (idx < NBUCK) ? hist[idx] : 0ull;
            int k = (int)((h >> 40) & 0xFFFFFull);
            int inck = k;
            #pragma unroll
            for (int off = 1; off < 32; off <<= 1) {
                int v = __shfl_up_sync(0xffffffffu, inck, off);
                if (lane >= off) inck += v;
            }
            int tot = __shfl_sync(0xffffffffu, inck, 31);
            unsigned m = __ballot_sync(0xffffffffu, c2cum + inck >= 8);
            if (m) { b1 = min(pos + (__ffs(m) - 1), NBUCK-1); done = true; }
            else   { c2cum += tot; pos += 32; }
        }
        if (lane == 0) g_b1[b] = b1;
    }
    if (t == 0) {
        g_b0[b] = b0;
        g_Sbefore[b] = (float)s_Sb;
        g_wcount[b] = 0;                 // reset for kGather's atomics
        if (b0 == NBUCK) g_b1[b] = -1;   // no crossing: accept all valid
    }
}

// ---- phase-1 decisions + gather window items (2 px / thread) ----
__global__ void kGather(float* __restrict__ out_sel) {
    int q = blockIdx.x * blockDim.x + threadIdx.x;   // NP/2 threads
    int p0 = q << 1;
    int b = p0 >> 16;
    uint2 d2 = *(const uint2*)(g_dsc + p0);
    uchar2 gg = *(const uchar2*)(g_g8 + p0);
    int b0 = g_b0[b], b1 = g_b1[b];
    unsigned dsc[2] = {d2.x, d2.y};
    int gv[2] = {gg.x, gg.y};
    signed char sm[2]; float so[2];
    #pragma unroll
    for (int k = 0; k < 2; k++) {
        bool valid = dsc[k] < 0x80000000u;
        int bucket = (int)(dsc[k] >> 16);
        bool acc = valid && bucket < b0;
        sm[k] = acc ? (signed char)gv[k] : (signed char)-1;
        so[k] = acc ? (float)gv[k] : -1.0f;
        if (valid && bucket >= b0 && bucket <= b1) {
            int i = atomicAdd(&g_wcount[b], 1);
            if (i < WCAP)
                g_window[b*WCAP + i] = ((unsigned long long)dsc[k] << 24)
                    | ((unsigned long long)((p0 + k) & 0xFFFF) << 8)
                    | (unsigned long long)gv[k];
        }
    }
    *(char2*)(g_selmap + p0) = make_char2(sm[0], sm[1]);
    *(float2*)(out_sel + p0) = make_float2(so[0], so[1]);
}

// ---- ranking sort + PARALLEL prefix-based greedy + tiny serial tail ----
__global__ void kWindow(const void* __restrict__ budget_p, float* __restrict__ out_sel) {
    __shared__ unsigned long long sk[WCAP];   // sorted window keys
    __shared__ int sp[WCAP];                  // inclusive cost prefix
    __shared__ int s_tsum[64];                // per-thread-chunk sums (512 thr /8)
    __shared__ int s_i1;
    int b = blockIdx.x, t = threadIdx.x;
    int n = min(g_wcount[b], WCAP);
    float budget = load_budget(budget_p) / (float)NB;
    float base = g_Sbefore[b];

    for (int i = t; i < n; i += 512) sk[i] = g_window[b*WCAP + i];
    if (t == 0) s_i1 = n;
    __syncthreads();

    // exact ranking sort (unique keys -> permutation)
    unsigned long long myk[8]; int myr[8]; int cnt = 0;
    for (int i = t; i < n; i += 512) {
        unsigned long long k = sk[i];
        int r = 0;
        for (int j = 0; j < n; j++) r += (sk[j] < k);
        myk[cnt] = k; myr[cnt] = r; cnt++;
    }
    __syncthreads();
    for (int q = 0; q < cnt; q++) sk[myr[q]] = myk[q];
    __syncthreads();

    // block-wide inclusive prefix sum of costs over contiguous 8-item chunks
    int lo = t * 8, hi = min(lo + 8, n);
    int run = 0;
    for (int i = lo; i < hi; i++) { run += cost_of((int)(sk[i] & 0xFFu)); sp[i] = run; }
    if ((t & 7) == 0) { }   // (no-op, keeps layout clear)
    // scan the 512 chunk totals hierarchically via 64-entry smem of warp sums
    int lane = t & 31, wid = t >> 5;
    int tot = run;
    int inc = tot;
    #pragma unroll
    for (int off = 1; off < 32; off <<= 1) {
        int v = __shfl_up_sync(0xffffffffu, inc, off);
        if (lane >= off) inc += v;
    }
    if (lane == 31) s_tsum[wid] = inc;
    __syncthreads();
    if (wid == 0 && lane < 16) {
        int w = s_tsum[lane];
        #pragma unroll
        for (int off = 1; off < 16; off <<= 1) {
            int v = __shfl_up_sync(0xffffu, w, off);
            if (lane >= off) w += v;
        }
        s_tsum[lane] = w;
    }
    __syncthreads();
    int chunk_off = (inc - tot) + ((wid > 0) ? s_tsum[wid-1] : 0);
    for (int i = lo; i < hi; i++) sp[i] += chunk_off;
    __syncthreads();

    // first rejection index: first i with base + sp[i] > budget
    for (int i = lo; i < hi; i++) {
        if (base + (float)sp[i] > budget) { atomicMin(&s_i1, i); break; }
    }
    __syncthreads();
    int i1 = s_i1;

    // parallel accept for i < i1
    for (int i = t; i < i1; i += 512) {
        unsigned long long k = sk[i];
        int g   = (int)(k & 0xFFu);
        int p   = b * HWPX + (int)((k >> 8) & 0xFFFFu);
        g_selmap[p] = (signed char)g;
        out_sel[p]  = (float)g;
    }

    // tiny serial tail from i1 (capacity < 4; breaks after <=3 cost-1 accepts)
    if (t == 0 && i1 < n) {
        float usage = base + (float)(i1 > 0 ? sp[i1-1] : 0);
        for (int i = i1; i < n; i++) {
            if (usage + 1.0f > budget) break;
            unsigned long long k = sk[i];
            int g = (int)(k & 0xFFu);
            float c = (float)cost_of(g);
            if (usage + c <= budget) {
                usage += c;
                int p = b * HWPX + (int)((k >> 8) & 0xFFFFu);
                g_selmap[p] = (signed char)g;
                out_sel[p]  = (float)g;
            }
        }
    }
}

// ---- big HBM-bound masked copy (frozen R3 winner) + hist re-zero for next replay ----
__global__ void kMaskedCopy(const float* __restrict__ collab, float* __restrict__ out) {
    int tid = blockIdx.x * blockDim.x + threadIdx.x;
    if (tid < (int)(sizeof(g_hist)/sizeof(uint4)))      // 81920 threads zero g_hist
        ((uint4*)g_hist)[tid] = make_uint4(0u, 0u, 0u, 0u);
    int row = tid >> 14;               // b*256 + c
    int o   = (tid & 16383) << 2;      // hw offset, multiple of 4
    int c   = row & 255;
    int b   = row >> 8;
    int grp = (c < 64) ? 0 : (c < 192) ? 1 : 2;
    char4 s4 = *(const char4*)(g_selmap + b * HWPX + o);
    bool m0 = (s4.x == grp), m1 = (s4.y == grp), m2 = (s4.z == grp), m3 = (s4.w == grp);
    float4 v = make_float4(0.f, 0.f, 0.f, 0.f);
    size_t idx = ((size_t)row << 16) + (size_t)o;
    if (m0 | m1 | m2 | m3) {
        v = *(const float4*)(collab + idx);
        if (!m0) v.x = 0.f;
        if (!m1) v.y = 0.f;
        if (!m2) v.z = 0.f;
        if (!m3) v.w = 0.f;
    }
    *(float4*)(out + idx) = v;
}

extern "C" void kernel_launch(void* const* d_in, const int* in_sizes, int n_in,
                              void* d_out, int out_size) {
    const float* collab = (const float*)d_in[0];
    const float* util   = (const float*)d_in[1];
    const void*  budget = d_in[2];
    float* out     = (float*)d_out;
    float* out_sel = out + (size_t)NP * NCH;

    kArgmax<<<NP/2/256, 256>>>(util);
    kFindWindow<<<NB, 1024>>>(budget);
    kGather<<<NP/2/256, 256>>>(out_sel);
    kWindow<<<NB, 512>>>(budget, out_sel);
    kMaskedCopy<<<(NP/4)*NCH/256, 256>>>(collab, out);
}

// round 10
// speedup vs baseline: 1.1867x; 1.0505x over previous
#include <cuda_runtime.h>
#include <cstdint>

#define NB      5
#define HWPX    65536
#define NP      (NB*HWPX)
#define NCH     256
#define BSHIFT  14                    // bucket = dsc >> 14 (18-bit buckets)
#define NBUCK   131072                // valid dsc < 0x80000000 -> bucket < 131072
#define TILESZ  4096
#define NTILE   (NBUCK/TILESZ)        // 32
#define WCAP    4096

// ---- static device scratch (allocation-free; zero-initialized at load) ----
__device__ unsigned int       g_dsc[NP];           // descending-order key of best utility
__device__ unsigned char      g_g8[NP];            // argmax group 0/1/2
__device__ signed char        g_selmap[NP];        // accepted group or -1
__device__ unsigned long long g_hist[NB*NBUCK];    // packed: cost | c1<<20 | c2<<40
__device__ unsigned long long g_window[NB*WCAP];
__device__ int                g_wcount[NB];
__device__ int                g_b0[NB], g_b1[NB];
__device__ float              g_Sbefore[NB];

__device__ __forceinline__ float load_budget(const void* ptr) {
    int iv = *(const int*)ptr;                       // int32 or float32 scalar
    if (iv > 0 && iv < 100000000) return (float)iv;
    return __int_as_float(iv);
}
__device__ __forceinline__ int cost_of(int g) { return (g == 0) ? 4 : (g == 1) ? 2 : 1; }

__device__ __forceinline__ void do_pixel(int p, float u0, float u1, float u2,
                                         unsigned* dsc_o, unsigned char* g_o) {
    int g = 0; float bu = u0;
    if (u1 > bu) { bu = u1; g = 1; }   // strict >: first max wins (jnp.argmax)
    if (u2 > bu) { bu = u2; g = 2; }
    bool valid = bu > 0.0f;
    unsigned int x = __float_as_uint(bu);
    unsigned int dsc = ~((x & 0x80000000u) ? ~x : (x | 0x80000000u)); // descending map
    if (!valid) dsc = 0xFFFFFFFFu;
    *dsc_o = dsc; *g_o = (unsigned char)g;
    if (valid) {
        unsigned long long inc = (unsigned long long)cost_of(g)
            | ((unsigned long long)(g == 1) << 20)
            | ((unsigned long long)(g == 2) << 40);
        atomicAdd(&g_hist[(size_t)(p >> 16) * NBUCK + (dsc >> BSHIFT)], inc);
    }
}

// ---- per-pixel argmax + packed histogram, 2 px / thread ----
__global__ void kArgmax(const float* __restrict__ util) {
    int q  = blockIdx.x * blockDim.x + threadIdx.x;   // NP/2 threads
    int p0 = q << 1;
    const float2* u = (const float2*)(util + 3 * (size_t)p0);   // 6 floats = 3x float2
    float2 a = u[0], b = u[1], c = u[2];
    unsigned d2[2]; unsigned char gg[2];
    do_pixel(p0 + 0, a.x, a.y, b.x, &d2[0], &gg[0]);
    do_pixel(p0 + 1, b.y, c.x, c.y, &d2[1], &gg[1]);
    *(uint2*)(g_dsc + p0) = make_uint2(d2[0], d2[1]);
    *(uchar2*)(g_g8 + p0) = make_uchar2(gg[0], gg[1]);
}

// ---- 1 block (1024 thr) per batch: tile sums + crossing b0 + window end b1 ----
__global__ void kFindWindow(const void* __restrict__ budget_p) {
    __shared__ unsigned s_tile[NTILE];
    __shared__ unsigned s_wsum[32];
    __shared__ int s_ctile, s_b0;
    __shared__ unsigned s_cumbase, s_Sb;

    int b = blockIdx.x, t = threadIdx.x;
    int wid = t >> 5, lane = t & 31;
    float budget = load_budget(budget_p) / (float)NB;
    const unsigned long long* hist = g_hist + (size_t)b * NBUCK;

    // warp w sums tile w (4096 buckets), coalesced
    unsigned sum = 0;
    #pragma unroll 8
    for (int j = 0; j < TILESZ/32; j++)
        sum += (unsigned)(hist[wid*TILESZ + j*32 + lane] & 0xFFFFFu);
    #pragma unroll
    for (int off = 16; off > 0; off >>= 1) sum += __shfl_down_sync(0xffffffffu, sum, off);
    if (lane == 0) s_tile[wid] = sum;
    if (t == 0) { s_ctile = -1; s_cumbase = 0; s_b0 = NBUCK; s_Sb = 0; }
    __syncthreads();

    if (t == 0) {   // tile-level crossing
        unsigned cum = 0;
        for (int q = 0; q < NTILE; q++) {
            unsigned c = s_tile[q];
            if ((float)(cum + c) > budget) { s_ctile = q; s_cumbase = cum; break; }
            cum += c;
        }
    }
    __syncthreads();
    int ctile = s_ctile;

    if (ctile >= 0) {   // in-tile scan: 4 buckets per thread over 4096 buckets
        int base = ctile*TILESZ + t*4;
        unsigned c4[4]; unsigned s = 0;
        #pragma unroll
        for (int k = 0; k < 4; k++) { c4[k] = (unsigned)(hist[base+k] & 0xFFFFFu); s += c4[k]; }
        unsigned inc = s;
        #pragma unroll
        for (int off = 1; off < 32; off <<= 1) {
            unsigned v = __shfl_up_sync(0xffffffffu, inc, off);
            if (lane >= off) inc += v;
        }
        if (lane == 31) s_wsum[wid] = inc;
        __syncthreads();
        if (wid == 0) {
            unsigned w = s_wsum[lane];
            #pragma unroll
            for (int off = 1; off < 32; off <<= 1) {
                unsigned v = __shfl_up_sync(0xffffffffu, w, off);
                if (lane >= off) w += v;
            }
            s_wsum[lane] = w;
        }
        __syncthreads();
        unsigned cum = s_cumbase + (inc - s) + ((wid > 0) ? s_wsum[wid-1] : 0u);
        #pragma unroll
        for (int k = 0; k < 4; k++) {   // unique first crossing among this thread's 4
            unsigned nxt = cum + c4[k];
            if ((float)nxt > budget && (float)cum <= budget) { s_b0 = base + k; s_Sb = cum; }
            cum = nxt;
        }
        __syncthreads();
    }

    int b0 = s_b0;
    if (wid == 0 && b0 < NBUCK) {
        // extend window bucket-by-bucket until >=8 cost-1 items beyond b0
        int c2cum = 0, pos = b0 + 1, b1 = NBUCK-1; bool done = false;
        while (!done && pos < NBUCK) {
            int idx = pos + lane;
            unsigned long long h = (idx < NBUCK) ? hist[idx] : 0ull;
            int k = (int)((h >> 40) & 0xFFFFFull);
            int inck = k;
            #pragma unroll
            for (int off = 1; off < 32; off <<= 1) {
                int v = __shfl_up_sync(0xffffffffu, inck, off);
                if (lane >= off) inck += v;
            }
            int tot = __shfl_sync(0xffffffffu, inck, 31);
            unsigned m = __ballot_sync(0xffffffffu, c2cum + inck >= 8);
            if (m) { b1 = min(pos + (__ffs(m) - 1), NBUCK-1); done = true; }
            else   { c2cum += tot; pos += 32; }
        }
        if (lane == 0) g_b1[b] = b1;
    }
    if (t == 0) {
        g_b0[b] = b0;
        g_Sbefore[b] = (float)s_Sb;
        g_wcount[b] = 0;                 // reset for kGather's atomics
        if (b0 == NBUCK) g_b1[b] = -1;   // no crossing: accept all valid
    }
}

// ---- phase-1 decisions + gather window items (2 px / thread) ----
__global__ void kGather(float* __restrict__ out_sel) {
    int q = blockIdx.x * blockDim.x + threadIdx.x;   // NP/2 threads
    int p0 = q << 1;
    int b = p0 >> 16;
    uint2 d2 = *(const uint2*)(g_dsc + p0);
    uchar2 gg = *(const uchar2*)(g_g8 + p0);
    int b0 = g_b0[b], b1 = g_b1[b];
    unsigned dsc[2] = {d2.x, d2.y};
    int gv[2] = {gg.x, gg.y};
    signed char sm[2]; float so[2];
    #pragma unroll
    for (int k = 0; k < 2; k++) {
        bool valid = dsc[k] < 0x80000000u;
        int bucket = (int)(dsc[k] >> BSHIFT);
        bool acc = valid && bucket < b0;
        sm[k] = acc ? (signed char)gv[k] : (signed char)-1;
        so[k] = acc ? (float)gv[k] : -1.0f;
        if (valid && bucket >= b0 && bucket <= b1) {
            int i = atomicAdd(&g_wcount[b], 1);
            if (i < WCAP)
                g_window[b*WCAP + i] = ((unsigned long long)dsc[k] << 24)
                    | ((unsigned long long)((p0 + k) & 0xFFFF) << 8)
                    | (unsigned long long)gv[k];
        }
    }
    *(char2*)(g_selmap + p0) = make_char2(sm[0], sm[1]);
    *(float2*)(out_sel + p0) = make_float2(so[0], so[1]);
}

// ---- ranking sort + parallel prefix-based greedy + tiny serial tail ----
__global__ void kWindow(const void* __restrict__ budget_p, float* __restrict__ out_sel) {
    __shared__ unsigned long long sk[WCAP];   // sorted window keys
    __shared__ int sp[WCAP];                  // inclusive cost prefix
    __shared__ int s_tsum[64];
    __shared__ int s_i1;
    int b = blockIdx.x, t = threadIdx.x;
    int n = min(g_wcount[b], WCAP);
    float budget = load_budget(budget_p) / (float)NB;
    float base = g_Sbefore[b];

    for (int i = t; i < n; i += 512) sk[i] = g_window[b*WCAP + i];
    if (t == 0) s_i1 = n;
    __syncthreads();

    // exact ranking sort (unique keys -> permutation)
    unsigned long long myk[8]; int myr[8]; int cnt = 0;
    for (int i = t; i < n; i += 512) {
        unsigned long long k = sk[i];
        int r = 0;
        for (int j = 0; j < n; j++) r += (sk[j] < k);
        myk[cnt] = k; myr[cnt] = r; cnt++;
    }
    __syncthreads();
    for (int q = 0; q < cnt; q++) sk[myr[q]] = myk[q];
    __syncthreads();

    // block-wide inclusive prefix sum of costs over contiguous 8-item chunks
    int lo = t * 8, hi = min(lo + 8, n);
    int run = 0;
    for (int i = lo; i < hi; i++) { run += cost_of((int)(sk[i] & 0xFFu)); sp[i] = run; }
    int lane = t & 31, wid = t >> 5;
    int tot = run, inc = tot;
    #pragma unroll
    for (int off = 1; off < 32; off <<= 1) {
        int v = __shfl_up_sync(0xffffffffu, inc, off);
        if (lane >= off) inc += v;
    }
    if (lane == 31) s_tsum[wid] = inc;
    __syncthreads();
    if (wid == 0 && lane < 16) {
        int w = s_tsum[lane];
        #pragma unroll
        for (int off = 1; off < 16; off <<= 1) {
            int v = __shfl_up_sync(0xffffu, w, off);
            if (lane >= off) w += v;
        }
        s_tsum[lane] = w;
    }
    __syncthreads();
    int chunk_off = (inc - tot) + ((wid > 0) ? s_tsum[wid-1] : 0);
    for (int i = lo; i < hi; i++) sp[i] += chunk_off;
    __syncthreads();

    // first rejection index: first i with base + sp[i] > budget
    for (int i = lo; i < hi; i++) {
        if (base + (float)sp[i] > budget) { atomicMin(&s_i1, i); break; }
    }
    __syncthreads();
    int i1 = s_i1;

    // parallel accept for i < i1
    for (int i = t; i < i1; i += 512) {
        unsigned long long k = sk[i];
        int g   = (int)(k & 0xFFu);
        int p   = b * HWPX + (int)((k >> 8) & 0xFFFFu);
        g_selmap[p] = (signed char)g;
        out_sel[p]  = (float)g;
    }

    // tiny serial tail from i1 (capacity < 4; breaks after <=3 cost-1 accepts)
    if (t == 0 && i1 < n) {
        float usage = base + (float)(i1 > 0 ? sp[i1-1] : 0);
        for (int i = i1; i < n; i++) {
            if (usage + 1.0f > budget) break;
            unsigned long long k = sk[i];
            int g = (int)(k & 0xFFu);
            float c = (float)cost_of(g);
            if (usage + c <= budget) {
                usage += c;
                int p = b * HWPX + (int)((k >> 8) & 0xFFFFu);
                g_selmap[p] = (signed char)g;
                out_sel[p]  = (float)g;
            }
        }
    }
}

// ---- big HBM-bound masked copy (frozen R3 winner) + hist re-zero for next replay ----
__global__ void kMaskedCopy(const float* __restrict__ collab, float* __restrict__ out) {
    int tid = blockIdx.x * blockDim.x + threadIdx.x;
    if (tid < (int)(sizeof(g_hist)/sizeof(uint4)))      // 327680 threads zero g_hist
        ((uint4*)g_hist)[tid] = make_uint4(0u, 0u, 0u, 0u);
    int row = tid >> 14;               // b*256 + c
    int o   = (tid & 16383) << 2;      // hw offset, multiple of 4
    int c   = row & 255;
    int b   = row >> 8;
    int grp = (c < 64) ? 0 : (c < 192) ? 1 : 2;
    char4 s4 = *(const char4*)(g_selmap + b * HWPX + o);
    bool m0 = (s4.x == grp), m1 = (s4.y == grp), m2 = (s4.z == grp), m3 = (s4.w == grp);
    float4 v = make_float4(0.f, 0.f, 0.f, 0.f);
    size_t idx = ((size_t)row << 16) + (size_t)o;
    if (m0 | m1 | m2 | m3) {
        v = *(const float4*)(collab + idx);
        if (!m0) v.x = 0.f;
        if (!m1) v.y = 0.f;
        if (!m2) v.z = 0.f;
        if (!m3) v.w = 0.f;
    }
    *(float4*)(out + idx) = v;
}

extern "C" void kernel_launch(void* const* d_in, const int* in_sizes, int n_in,
                              void* d_out, int out_size) {
    const float* collab = (const float*)d_in[0];
    const float* util   = (const float*)d_in[1];
    const void*  budget = d_in[2];
    float* out     = (float*)d_out;
    float* out_sel = out + (size_t)NP * NCH;

    kArgmax<<<NP/2/256, 256>>>(util);
    kFindWindow<<<NB, 1024>>>(budget);
    kGather<<<NP/2/256, 256>>>(out_sel);
    kWindow<<<NB, 512>>>(budget, out_sel);
    kMaskedCopy<<<(NP/4)*NCH/256, 256>>>(collab, out);
}